// round 1
// baseline (speedup 1.0000x reference)
#include <cuda_runtime.h>
#include <math.h>

// Problem constants (fixed by the reference)
#define S_LEN   2048
#define EMB     1024
#define NH      16
#define HD      64
#define BATCH   2
#define M_ROWS  (BATCH * S_LEN)   // 4096

// Scratch (no cudaMalloc allowed): q,k,v in [B,h,S,d]; z in [B,S,E]
__device__ float g_q[BATCH * NH * S_LEN * HD];
__device__ float g_k[BATCH * NH * S_LEN * HD];
__device__ float g_v[BATCH * NH * S_LEN * HD];
__device__ float g_z[BATCH * S_LEN * EMB];

// ---------------------------------------------------------------------------
// GEMM: C = A[M,K] @ B[K,N] + bias[N]
//   MODE 0: C row-major [M,N]
//   MODE 1: scatter to [B, h, S, d]  (m = b*S + s ; n = head*64 + dd)
// Tiling: 128x128 block tile, BK=16, 256 threads, 8x8 per thread (2x2 of 4x4).
// ---------------------------------------------------------------------------
template <int MODE>
__global__ __launch_bounds__(256)
void gemm_kernel(const float* __restrict__ A,
                 const float* __restrict__ B,
                 const float* __restrict__ bias,
                 float* __restrict__ C,
                 int M, int N, int K)
{
    __shared__ float As[16][132];   // transposed A tile, padded (132 % 4 == 0)
    __shared__ float Bs[16][128];

    const int tid = threadIdx.x;
    const int tx = tid & 15;        // 0..15  -> column group
    const int ty = tid >> 4;        // 0..15  -> row group
    const int m0 = blockIdx.y * 128;
    const int n0 = blockIdx.x * 128;

    // A tile load mapping: rows aRow, aRow+64 ; 4 consecutive k at aK
    const int aRow = tid >> 2;        // 0..63
    const int aK   = (tid & 3) * 4;   // 0,4,8,12
    // B tile load mapping: rows bRow, bRow+8 ; 4 consecutive n at bCol
    const int bRow = tid >> 5;        // 0..7
    const int bCol = (tid & 31) * 4;  // 0..124

    float acc[8][8];
#pragma unroll
    for (int i = 0; i < 8; i++)
#pragma unroll
        for (int j = 0; j < 8; j++) acc[i][j] = 0.f;

    for (int k0 = 0; k0 < K; k0 += 16) {
        // Global loads into registers first (no smem hazard)
        const float4 a0 = *(const float4*)(A + (size_t)(m0 + aRow)      * K + k0 + aK);
        const float4 a1 = *(const float4*)(A + (size_t)(m0 + aRow + 64) * K + k0 + aK);
        const float4 b0 = *(const float4*)(B + (size_t)(k0 + bRow)     * N + n0 + bCol);
        const float4 b1 = *(const float4*)(B + (size_t)(k0 + bRow + 8) * N + n0 + bCol);

        __syncthreads();   // previous iteration's compute done before overwrite

        As[aK + 0][aRow] = a0.x;  As[aK + 1][aRow] = a0.y;
        As[aK + 2][aRow] = a0.z;  As[aK + 3][aRow] = a0.w;
        As[aK + 0][aRow + 64] = a1.x;  As[aK + 1][aRow + 64] = a1.y;
        As[aK + 2][aRow + 64] = a1.z;  As[aK + 3][aRow + 64] = a1.w;
        *(float4*)&Bs[bRow][bCol]     = b0;
        *(float4*)&Bs[bRow + 8][bCol] = b1;

        __syncthreads();

#pragma unroll
        for (int kk = 0; kk < 16; kk++) {
            const float4 ra0 = *(const float4*)&As[kk][ty * 4];
            const float4 ra1 = *(const float4*)&As[kk][64 + ty * 4];
            const float4 rb0 = *(const float4*)&Bs[kk][tx * 4];
            const float4 rb1 = *(const float4*)&Bs[kk][64 + tx * 4];
            const float ra[8] = {ra0.x, ra0.y, ra0.z, ra0.w, ra1.x, ra1.y, ra1.z, ra1.w};
            const float rb[8] = {rb0.x, rb0.y, rb0.z, rb0.w, rb1.x, rb1.y, rb1.z, rb1.w};
#pragma unroll
            for (int i = 0; i < 8; i++)
#pragma unroll
                for (int j = 0; j < 8; j++)
                    acc[i][j] = fmaf(ra[i], rb[j], acc[i][j]);
        }
    }

    // Epilogue
#pragma unroll
    for (int i = 0; i < 8; i++) {
        const int m = m0 + ((i < 4) ? (ty * 4 + i) : (64 + ty * 4 + i - 4));
#pragma unroll
        for (int j = 0; j < 8; j++) {
            const int n = n0 + ((j < 4) ? (tx * 4 + j) : (64 + tx * 4 + j - 4));
            const float v = acc[i][j] + bias[n];
            if (MODE == 0) {
                C[(size_t)m * N + n] = v;
            } else {
                const int b    = m >> 11;    // m / 2048
                const int s    = m & 2047;
                const int head = n >> 6;     // n / 64
                const int dd   = n & 63;
                C[((((size_t)b * NH + head) * S_LEN) + s) * HD + dd] = v;
            }
        }
    }
}

// ---------------------------------------------------------------------------
// Flash attention, fp32, one query row per thread.
// Q,K,V in [B,h,S,d]; Z written in [B,S,E]. Online softmax, KV tile = 16.
// ---------------------------------------------------------------------------
__global__ __launch_bounds__(128, 2)
void attn_kernel(const float* __restrict__ Q,
                 const float* __restrict__ Kp,
                 const float* __restrict__ Vp,
                 float* __restrict__ Z)
{
    __shared__ float Ks[16][64];
    __shared__ float Vs[16][64];

    const int tid  = threadIdx.x;
    const int bh   = blockIdx.y;          // 0..31
    const int b    = bh >> 4;
    const int head = bh & 15;
    const int qi   = blockIdx.x * 128 + tid;

    const float* qrow = Q + ((size_t)bh * S_LEN + qi) * HD;
    float q[64];
#pragma unroll
    for (int i = 0; i < 16; i++) {
        const float4 t = *(const float4*)(qrow + i * 4);
        q[i * 4 + 0] = t.x; q[i * 4 + 1] = t.y; q[i * 4 + 2] = t.z; q[i * 4 + 3] = t.w;
    }

    float o[64];
#pragma unroll
    for (int i = 0; i < 64; i++) o[i] = 0.f;
    float mval = -1e30f, l = 0.f;

    const float* Kbase = Kp + (size_t)bh * S_LEN * HD;
    const float* Vbase = Vp + (size_t)bh * S_LEN * HD;

    for (int kv0 = 0; kv0 < S_LEN; kv0 += 16) {
        __syncthreads();
        // 16x64 floats = 256 float4 per tile; 128 threads -> 2 each (for K and V)
#pragma unroll
        for (int i = 0; i < 2; i++) {
            const int f = tid + i * 128;       // 0..255
            const int r = f >> 4;              // 0..15
            const int c = (f & 15) * 4;        // 0..60
            *(float4*)&Ks[r][c] = *(const float4*)(Kbase + (size_t)(kv0 + r) * HD + c);
            *(float4*)&Vs[r][c] = *(const float4*)(Vbase + (size_t)(kv0 + r) * HD + c);
        }
        __syncthreads();

        float s[16];
#pragma unroll
        for (int j = 0; j < 16; j++) {
            float s0 = 0.f, s1 = 0.f, s2 = 0.f, s3 = 0.f;
#pragma unroll
            for (int dd = 0; dd < 64; dd += 4) {
                s0 = fmaf(q[dd + 0], Ks[j][dd + 0], s0);
                s1 = fmaf(q[dd + 1], Ks[j][dd + 1], s1);
                s2 = fmaf(q[dd + 2], Ks[j][dd + 2], s2);
                s3 = fmaf(q[dd + 3], Ks[j][dd + 3], s3);
            }
            s[j] = (s0 + s1) + (s2 + s3);
        }

        float tm = s[0];
#pragma unroll
        for (int j = 1; j < 16; j++) tm = fmaxf(tm, s[j]);
        tm *= 0.125f;

        const float mn   = fmaxf(mval, tm);
        const float corr = __expf(mval - mn);   // exp(-huge)=0 on first tile
        l *= corr;
#pragma unroll
        for (int dd = 0; dd < 64; dd++) o[dd] *= corr;

#pragma unroll
        for (int j = 0; j < 16; j++) {
            const float p = __expf(fmaf(s[j], 0.125f, -mn));
            l += p;
#pragma unroll
            for (int dd = 0; dd < 64; dd++)
                o[dd] = fmaf(p, Vs[j][dd], o[dd]);
        }
        mval = mn;
    }

    const float inv = 1.f / l;
    float* zrow = Z + ((size_t)(b * S_LEN + qi)) * EMB + head * HD;
#pragma unroll
    for (int i = 0; i < 16; i++) {
        float4 t;
        t.x = o[i * 4 + 0] * inv; t.y = o[i * 4 + 1] * inv;
        t.z = o[i * 4 + 2] * inv; t.w = o[i * 4 + 3] * inv;
        *(float4*)(zrow + i * 4) = t;
    }
}

// ---------------------------------------------------------------------------
// Launch
// ---------------------------------------------------------------------------
extern "C" void kernel_launch(void* const* d_in, const int* in_sizes, int n_in,
                              void* d_out, int out_size)
{
    const float* query = (const float*)d_in[0];
    const float* key_  = (const float*)d_in[1];
    const float* value = (const float*)d_in[2];
    const float* Wq = (const float*)d_in[3];
    const float* bq = (const float*)d_in[4];
    const float* Wk = (const float*)d_in[5];
    const float* bk = (const float*)d_in[6];
    const float* Wv = (const float*)d_in[7];
    const float* bv = (const float*)d_in[8];
    const float* Wo = (const float*)d_in[9];
    const float* bo = (const float*)d_in[10];
    float* out = (float*)d_out;

    float *q, *k, *v, *z;
    cudaGetSymbolAddress((void**)&q, g_q);
    cudaGetSymbolAddress((void**)&k, g_k);
    cudaGetSymbolAddress((void**)&v, g_v);
    cudaGetSymbolAddress((void**)&z, g_z);

    const dim3 gemmGrid(EMB / 128, M_ROWS / 128);   // (8, 32)
    const dim3 attnGrid(S_LEN / 128, BATCH * NH);   // (16, 32)

    gemm_kernel<1><<<gemmGrid, 256>>>(query, Wq, bq, q, M_ROWS, EMB, EMB);
    gemm_kernel<1><<<gemmGrid, 256>>>(key_,  Wk, bk, k, M_ROWS, EMB, EMB);
    gemm_kernel<1><<<gemmGrid, 256>>>(value, Wv, bv, v, M_ROWS, EMB, EMB);
    attn_kernel<<<attnGrid, 128>>>(q, k, v, z);
    gemm_kernel<0><<<gemmGrid, 256>>>(z, Wo, bo, out, M_ROWS, EMB, EMB);
}

// round 4
// speedup vs baseline: 2.4867x; 2.4867x over previous
#include <cuda_runtime.h>
#include <math.h>

#define S_LEN   2048
#define EMB     1024
#define NH      16
#define HD      64
#define BATCH   2
#define M_ROWS  (BATCH * S_LEN)   // 4096

// Scratch: q,k,v in [B,h,S,d]; z in [B,S,E]
__device__ float g_q[BATCH * NH * S_LEN * HD];
__device__ float g_k[BATCH * NH * S_LEN * HD];
__device__ float g_v[BATCH * NH * S_LEN * HD];
__device__ float g_z[BATCH * S_LEN * EMB];

// Round fp32 -> tf32 (RNA). cvt.rna.tf32.f32 needs a .b32 destination.
__device__ __forceinline__ unsigned tf32u(float x) {
    unsigned r;
    asm("cvt.rna.tf32.f32 %0, %1;" : "=r"(r) : "f"(x));
    return r;
}
__device__ __forceinline__ float tf32f(float x) {
    return __uint_as_float(tf32u(x));
}

// D += A(16x8) * B(8x8), tf32 inputs, fp32 accumulate.
__device__ __forceinline__ void mma8(float* d, const unsigned* a, const unsigned* b) {
    asm volatile(
        "mma.sync.aligned.m16n8k8.row.col.f32.tf32.tf32.f32 "
        "{%0,%1,%2,%3}, {%4,%5,%6,%7}, {%8,%9}, {%0,%1,%2,%3};\n"
        : "+f"(d[0]), "+f"(d[1]), "+f"(d[2]), "+f"(d[3])
        : "r"(a[0]), "r"(a[1]), "r"(a[2]), "r"(a[3]), "r"(b[0]), "r"(b[1]));
}

// ---------------------------------------------------------------------------
// tf32 tensor-core GEMM: C = A[M,K] @ B[K,N] + bias
//   MODE 0: row-major C[M,N];  MODE 1: scatter to [B,h,S,d]
// 128x128 block, BK=16, 8 warps (4x2), warp tile 32x64, m16n8k8.
// ---------------------------------------------------------------------------
template <int MODE>
__global__ __launch_bounds__(256)
void gemm_tc(const float* __restrict__ A, const float* __restrict__ B,
             const float* __restrict__ bias, float* __restrict__ C,
             int M, int N, int K)
{
    __shared__ float As[16][132];   // [k][m], padded: frag LDS conflict-free
    __shared__ float Bs[16][132];   // [k][n], padded

    const int tid  = threadIdx.x;
    const int warp = tid >> 5, lane = tid & 31;
    const int g = lane >> 2, tg = lane & 3;
    const int wm = (warp >> 1) * 32;     // warp row offset (4 warps in m)
    const int wn = (warp & 1) * 64;      // warp col offset (2 warps in n)
    const int m0 = blockIdx.y * 128, n0 = blockIdx.x * 128;

    float acc[2][8][4];
#pragma unroll
    for (int mt = 0; mt < 2; mt++)
#pragma unroll
        for (int nt = 0; nt < 8; nt++)
#pragma unroll
            for (int c = 0; c < 4; c++) acc[mt][nt][c] = 0.f;

    const int aRow = tid >> 2;        // 0..63
    const int aK   = (tid & 3) * 4;   // 0,4,8,12

    for (int k0 = 0; k0 < K; k0 += 16) {
        // Stage global loads in registers
        const float4 a0 = *(const float4*)(A + (size_t)(m0 + aRow)      * K + k0 + aK);
        const float4 a1 = *(const float4*)(A + (size_t)(m0 + aRow + 64) * K + k0 + aK);
        float4 bt[2];
        int br[2], bc[2];
#pragma unroll
        for (int i = 0; i < 2; i++) {
            const int f = i * 256 + tid;      // 0..511 float4 slots
            br[i] = f >> 5;                   // 0..15
            bc[i] = (f & 31) * 4;             // 0..124
            bt[i] = *(const float4*)(B + (size_t)(k0 + br[i]) * N + n0 + bc[i]);
        }

        __syncthreads();

        As[aK + 0][aRow] = tf32f(a0.x);  As[aK + 1][aRow] = tf32f(a0.y);
        As[aK + 2][aRow] = tf32f(a0.z);  As[aK + 3][aRow] = tf32f(a0.w);
        As[aK + 0][aRow + 64] = tf32f(a1.x);  As[aK + 1][aRow + 64] = tf32f(a1.y);
        As[aK + 2][aRow + 64] = tf32f(a1.z);  As[aK + 3][aRow + 64] = tf32f(a1.w);
#pragma unroll
        for (int i = 0; i < 2; i++) {
            Bs[br[i]][bc[i] + 0] = tf32f(bt[i].x);
            Bs[br[i]][bc[i] + 1] = tf32f(bt[i].y);
            Bs[br[i]][bc[i] + 2] = tf32f(bt[i].z);
            Bs[br[i]][bc[i] + 3] = tf32f(bt[i].w);
        }

        __syncthreads();

#pragma unroll
        for (int kk = 0; kk < 16; kk += 8) {
            unsigned af[2][4];
#pragma unroll
            for (int mt = 0; mt < 2; mt++) {
                const int mb = wm + mt * 16;
                af[mt][0] = __float_as_uint(As[kk + tg    ][mb + g    ]);
                af[mt][1] = __float_as_uint(As[kk + tg    ][mb + g + 8]);
                af[mt][2] = __float_as_uint(As[kk + tg + 4][mb + g    ]);
                af[mt][3] = __float_as_uint(As[kk + tg + 4][mb + g + 8]);
            }
#pragma unroll
            for (int nt = 0; nt < 8; nt++) {
                unsigned bf[2];
                bf[0] = __float_as_uint(Bs[kk + tg    ][wn + nt * 8 + g]);
                bf[1] = __float_as_uint(Bs[kk + tg + 4][wn + nt * 8 + g]);
                mma8(acc[0][nt], af[0], bf);
                mma8(acc[1][nt], af[1], bf);
            }
        }
    }

    // Epilogue
#pragma unroll
    for (int mt = 0; mt < 2; mt++)
#pragma unroll
        for (int nt = 0; nt < 8; nt++)
#pragma unroll
            for (int c = 0; c < 4; c++) {
                const int m = m0 + wm + mt * 16 + g + ((c >= 2) ? 8 : 0);
                const int n = n0 + wn + nt * 8 + 2 * tg + (c & 1);
                const float v = acc[mt][nt][c] + bias[n];
                if (MODE == 0) {
                    C[(size_t)m * N + n] = v;
                } else {
                    const int b    = m >> 11;
                    const int s    = m & 2047;
                    const int head = n >> 6;
                    const int dd   = n & 63;
                    C[((((size_t)b * NH + head) * S_LEN) + s) * HD + dd] = v;
                }
            }
}

// ---------------------------------------------------------------------------
// Flash attention, tf32 tensor cores. 64 q rows per block, 4 warps (16 each).
// KV tiles of 64 via smem. P reuses the K-tile smem (block sync in between).
// ---------------------------------------------------------------------------
__global__ __launch_bounds__(128)
void attn_tc(const float* __restrict__ Q, const float* __restrict__ Kp,
             const float* __restrict__ Vp, float* __restrict__ Z)
{
    __shared__ float Ks[64][68];   // K tile, later reused as P
    __shared__ float Vs[64][68];

    const int tid  = threadIdx.x;
    const int warp = tid >> 5, lane = tid & 31;
    const int g = lane >> 2, tg = lane & 3;
    const int bh   = blockIdx.y;
    const int b    = bh >> 4, head = bh & 15;
    const int q0   = blockIdx.x * 64;
    const int rlo  = warp * 16 + g;     // local row 0..63 (this thread's low row)

    // Q fragments, pre-scaled by 1/sqrt(64)=0.125, tf32-rounded.
    const float* qlo = Q + ((size_t)bh * S_LEN + q0 + rlo) * HD;
    const float* qhi = qlo + 8 * HD;
    unsigned qf[8][4];
#pragma unroll
    for (int kt = 0; kt < 8; kt++) {
        qf[kt][0] = tf32u(0.125f * qlo[kt * 8 + tg]);
        qf[kt][1] = tf32u(0.125f * qhi[kt * 8 + tg]);
        qf[kt][2] = tf32u(0.125f * qlo[kt * 8 + tg + 4]);
        qf[kt][3] = tf32u(0.125f * qhi[kt * 8 + tg + 4]);
    }

    float oacc[8][4];
#pragma unroll
    for (int nt = 0; nt < 8; nt++)
#pragma unroll
        for (int c = 0; c < 4; c++) oacc[nt][c] = 0.f;
    float m_lo = -1e30f, m_hi = -1e30f, l_lo = 0.f, l_hi = 0.f;

    const float* Kb = Kp + (size_t)bh * S_LEN * HD;
    const float* Vb = Vp + (size_t)bh * S_LEN * HD;

    for (int kv0 = 0; kv0 < S_LEN; kv0 += 64) {
        __syncthreads();   // previous tile fully consumed
#pragma unroll
        for (int i = 0; i < 8; i++) {
            const int f = i * 128 + tid;
            const int r = f >> 4, c = (f & 15) * 4;
            const float4 k4 = *(const float4*)(Kb + (size_t)(kv0 + r) * HD + c);
            const float4 v4 = *(const float4*)(Vb + (size_t)(kv0 + r) * HD + c);
            Ks[r][c + 0] = tf32f(k4.x); Ks[r][c + 1] = tf32f(k4.y);
            Ks[r][c + 2] = tf32f(k4.z); Ks[r][c + 3] = tf32f(k4.w);
            Vs[r][c + 0] = tf32f(v4.x); Vs[r][c + 1] = tf32f(v4.y);
            Vs[r][c + 2] = tf32f(v4.z); Vs[r][c + 3] = tf32f(v4.w);
        }
        __syncthreads();

        // S = Q @ K^T  (scaled already via Q)
        float sacc[8][4];
#pragma unroll
        for (int nt = 0; nt < 8; nt++)
#pragma unroll
            for (int c = 0; c < 4; c++) sacc[nt][c] = 0.f;
#pragma unroll
        for (int kt = 0; kt < 8; kt++) {
#pragma unroll
            for (int nt = 0; nt < 8; nt++) {
                unsigned bf[2];
                bf[0] = __float_as_uint(Ks[nt * 8 + g][kt * 8 + tg]);
                bf[1] = __float_as_uint(Ks[nt * 8 + g][kt * 8 + tg + 4]);
                mma8(sacc[nt], qf[kt], bf);
            }
        }

        // Online softmax (rows rlo and rlo+8)
        float rmax_lo = -1e30f, rmax_hi = -1e30f;
#pragma unroll
        for (int nt = 0; nt < 8; nt++) {
            rmax_lo = fmaxf(rmax_lo, fmaxf(sacc[nt][0], sacc[nt][1]));
            rmax_hi = fmaxf(rmax_hi, fmaxf(sacc[nt][2], sacc[nt][3]));
        }
        rmax_lo = fmaxf(rmax_lo, __shfl_xor_sync(0xffffffffu, rmax_lo, 1));
        rmax_lo = fmaxf(rmax_lo, __shfl_xor_sync(0xffffffffu, rmax_lo, 2));
        rmax_hi = fmaxf(rmax_hi, __shfl_xor_sync(0xffffffffu, rmax_hi, 1));
        rmax_hi = fmaxf(rmax_hi, __shfl_xor_sync(0xffffffffu, rmax_hi, 2));

        const float mn_lo = fmaxf(m_lo, rmax_lo);
        const float mn_hi = fmaxf(m_hi, rmax_hi);
        const float corr_lo = __expf(m_lo - mn_lo);
        const float corr_hi = __expf(m_hi - mn_hi);

        float rs_lo = 0.f, rs_hi = 0.f;
#pragma unroll
        for (int nt = 0; nt < 8; nt++) {
            sacc[nt][0] = __expf(sacc[nt][0] - mn_lo);
            sacc[nt][1] = __expf(sacc[nt][1] - mn_lo);
            sacc[nt][2] = __expf(sacc[nt][2] - mn_hi);
            sacc[nt][3] = __expf(sacc[nt][3] - mn_hi);
            rs_lo += sacc[nt][0] + sacc[nt][1];
            rs_hi += sacc[nt][2] + sacc[nt][3];
        }
        rs_lo += __shfl_xor_sync(0xffffffffu, rs_lo, 1);
        rs_lo += __shfl_xor_sync(0xffffffffu, rs_lo, 2);
        rs_hi += __shfl_xor_sync(0xffffffffu, rs_hi, 1);
        rs_hi += __shfl_xor_sync(0xffffffffu, rs_hi, 2);

        l_lo = l_lo * corr_lo + rs_lo;
        l_hi = l_hi * corr_hi + rs_hi;
#pragma unroll
        for (int nt = 0; nt < 8; nt++) {
            oacc[nt][0] *= corr_lo; oacc[nt][1] *= corr_lo;
            oacc[nt][2] *= corr_hi; oacc[nt][3] *= corr_hi;
        }
        m_lo = mn_lo; m_hi = mn_hi;

        __syncthreads();   // all warps done reading Ks before P overwrites it

        // Write P (tf32) into Ks region — each warp owns rows warp*16..+15
#pragma unroll
        for (int nt = 0; nt < 8; nt++) {
            Ks[rlo    ][nt * 8 + 2 * tg    ] = tf32f(sacc[nt][0]);
            Ks[rlo    ][nt * 8 + 2 * tg + 1] = tf32f(sacc[nt][1]);
            Ks[rlo + 8][nt * 8 + 2 * tg    ] = tf32f(sacc[nt][2]);
            Ks[rlo + 8][nt * 8 + 2 * tg + 1] = tf32f(sacc[nt][3]);
        }
        __syncwarp();

        // O += P @ V
#pragma unroll
        for (int kt = 0; kt < 8; kt++) {
            unsigned pf[4];
            pf[0] = __float_as_uint(Ks[rlo    ][kt * 8 + tg    ]);
            pf[1] = __float_as_uint(Ks[rlo + 8][kt * 8 + tg    ]);
            pf[2] = __float_as_uint(Ks[rlo    ][kt * 8 + tg + 4]);
            pf[3] = __float_as_uint(Ks[rlo + 8][kt * 8 + tg + 4]);
#pragma unroll
            for (int nt = 0; nt < 8; nt++) {
                unsigned bf[2];
                bf[0] = __float_as_uint(Vs[kt * 8 + tg    ][nt * 8 + g]);
                bf[1] = __float_as_uint(Vs[kt * 8 + tg + 4][nt * 8 + g]);
                mma8(oacc[nt], pf, bf);
            }
        }
    }

    const float inv_lo = 1.f / l_lo;
    const float inv_hi = 1.f / l_hi;
    float* zlo = Z + ((size_t)(b * S_LEN + q0 + rlo)) * EMB + head * HD;
    float* zhi = zlo + (size_t)8 * EMB;
#pragma unroll
    for (int nt = 0; nt < 8; nt++) {
        zlo[nt * 8 + 2 * tg    ] = oacc[nt][0] * inv_lo;
        zlo[nt * 8 + 2 * tg + 1] = oacc[nt][1] * inv_lo;
        zhi[nt * 8 + 2 * tg    ] = oacc[nt][2] * inv_hi;
        zhi[nt * 8 + 2 * tg + 1] = oacc[nt][3] * inv_hi;
    }
}

// ---------------------------------------------------------------------------
extern "C" void kernel_launch(void* const* d_in, const int* in_sizes, int n_in,
                              void* d_out, int out_size)
{
    const float* query = (const float*)d_in[0];
    const float* key_  = (const float*)d_in[1];
    const float* value = (const float*)d_in[2];
    const float* Wq = (const float*)d_in[3];
    const float* bq = (const float*)d_in[4];
    const float* Wk = (const float*)d_in[5];
    const float* bk = (const float*)d_in[6];
    const float* Wv = (const float*)d_in[7];
    const float* bv = (const float*)d_in[8];
    const float* Wo = (const float*)d_in[9];
    const float* bo = (const float*)d_in[10];
    float* out = (float*)d_out;

    float *q, *k, *v, *z;
    cudaGetSymbolAddress((void**)&q, g_q);
    cudaGetSymbolAddress((void**)&k, g_k);
    cudaGetSymbolAddress((void**)&v, g_v);
    cudaGetSymbolAddress((void**)&z, g_z);

    const dim3 gemmGrid(EMB / 128, M_ROWS / 128);   // (8, 32)
    const dim3 attnGrid(S_LEN / 64, BATCH * NH);    // (32, 32)

    gemm_tc<1><<<gemmGrid, 256>>>(query, Wq, bq, q, M_ROWS, EMB, EMB);
    gemm_tc<1><<<gemmGrid, 256>>>(key_,  Wk, bk, k, M_ROWS, EMB, EMB);
    gemm_tc<1><<<gemmGrid, 256>>>(value, Wv, bv, v, M_ROWS, EMB, EMB);
    attn_tc<<<attnGrid, 128>>>(q, k, v, z);
    gemm_tc<0><<<gemmGrid, 256>>>(z, Wo, bo, out, M_ROWS, EMB, EMB);
}

// round 5
// speedup vs baseline: 2.8755x; 1.1564x over previous
#include <cuda_runtime.h>
#include <math.h>

#define S_LEN   2048
#define EMB     1024
#define NH      16
#define HD      64
#define BATCH   2
#define M_ROWS  (BATCH * S_LEN)   // 4096

// Scratch: q,k,v in [B,h,S,d]; z in [B,S,E]
__device__ float g_q[BATCH * NH * S_LEN * HD];
__device__ float g_k[BATCH * NH * S_LEN * HD];
__device__ float g_v[BATCH * NH * S_LEN * HD];
__device__ float g_z[BATCH * S_LEN * EMB];

// Round fp32 -> tf32 (RNA). cvt.rna.tf32.f32 needs a .b32 destination.
__device__ __forceinline__ unsigned tf32u(float x) {
    unsigned r;
    asm("cvt.rna.tf32.f32 %0, %1;" : "=r"(r) : "f"(x));
    return r;
}
__device__ __forceinline__ float tf32f(float x) {
    return __uint_as_float(tf32u(x));
}

// D += A(16x8) * B(8x8), tf32 inputs, fp32 accumulate.
__device__ __forceinline__ void mma8(float* d, const unsigned* a, const unsigned* b) {
    asm volatile(
        "mma.sync.aligned.m16n8k8.row.col.f32.tf32.tf32.f32 "
        "{%0,%1,%2,%3}, {%4,%5,%6,%7}, {%8,%9}, {%0,%1,%2,%3};\n"
        : "+f"(d[0]), "+f"(d[1]), "+f"(d[2]), "+f"(d[3])
        : "r"(a[0]), "r"(a[1]), "r"(a[2]), "r"(a[3]), "r"(b[0]), "r"(b[1]));
}

// ---------------------------------------------------------------------------
// tf32 tensor-core GEMM, double-buffered smem: C = A[M,K] @ B[K,N] + bias
//   MODE 0: row-major C[M,N];  MODE 1: scatter to [B,h,S,d]
// 128x128 block, BK=16, 8 warps (4x2), warp tile 32x64, m16n8k8.
// ---------------------------------------------------------------------------
template <int MODE>
__global__ __launch_bounds__(256)
void gemm_tc(const float* __restrict__ A, const float* __restrict__ B,
             const float* __restrict__ bias, float* __restrict__ C,
             int M, int N, int K)
{
    __shared__ float As[2][16][132];   // [k][m], padded
    __shared__ float Bs[2][16][132];   // [k][n], padded

    const int tid  = threadIdx.x;
    const int warp = tid >> 5, lane = tid & 31;
    const int g = lane >> 2, tg = lane & 3;
    const int wm = (warp >> 1) * 32;
    const int wn = (warp & 1) * 64;
    const int m0 = blockIdx.y * 128, n0 = blockIdx.x * 128;

    float acc[2][8][4];
#pragma unroll
    for (int mt = 0; mt < 2; mt++)
#pragma unroll
        for (int nt = 0; nt < 8; nt++)
#pragma unroll
            for (int c = 0; c < 4; c++) acc[mt][nt][c] = 0.f;

    const int aRow = tid >> 2;        // 0..63
    const int aK   = (tid & 3) * 4;   // 0,4,8,12
    const int br0  = tid >> 5,           bc0 = (tid & 31) * 4;         // slots 0..255
    const int br1  = (256 + tid) >> 5,   bc1 = (tid & 31) * 4;         // slots 256..511

    // Prologue: stage tile 0 into buffer 0
    {
        const float4 a0 = *(const float4*)(A + (size_t)(m0 + aRow)      * K + aK);
        const float4 a1 = *(const float4*)(A + (size_t)(m0 + aRow + 64) * K + aK);
        const float4 b0 = *(const float4*)(B + (size_t)br0 * N + n0 + bc0);
        const float4 b1 = *(const float4*)(B + (size_t)br1 * N + n0 + bc1);
        As[0][aK + 0][aRow] = tf32f(a0.x);  As[0][aK + 1][aRow] = tf32f(a0.y);
        As[0][aK + 2][aRow] = tf32f(a0.z);  As[0][aK + 3][aRow] = tf32f(a0.w);
        As[0][aK + 0][aRow + 64] = tf32f(a1.x);  As[0][aK + 1][aRow + 64] = tf32f(a1.y);
        As[0][aK + 2][aRow + 64] = tf32f(a1.z);  As[0][aK + 3][aRow + 64] = tf32f(a1.w);
        Bs[0][br0][bc0 + 0] = tf32f(b0.x); Bs[0][br0][bc0 + 1] = tf32f(b0.y);
        Bs[0][br0][bc0 + 2] = tf32f(b0.z); Bs[0][br0][bc0 + 3] = tf32f(b0.w);
        Bs[0][br1][bc1 + 0] = tf32f(b1.x); Bs[0][br1][bc1 + 1] = tf32f(b1.y);
        Bs[0][br1][bc1 + 2] = tf32f(b1.z); Bs[0][br1][bc1 + 3] = tf32f(b1.w);
    }
    __syncthreads();

    for (int k0 = 0; k0 < K; k0 += 16) {
        const int buf = (k0 >> 4) & 1;
        const bool hasNext = (k0 + 16) < K;

        // Issue global loads for the NEXT tile before computing this one.
        float4 a0, a1, b0, b1;
        if (hasNext) {
            const int kn = k0 + 16;
            a0 = *(const float4*)(A + (size_t)(m0 + aRow)      * K + kn + aK);
            a1 = *(const float4*)(A + (size_t)(m0 + aRow + 64) * K + kn + aK);
            b0 = *(const float4*)(B + (size_t)(kn + br0) * N + n0 + bc0);
            b1 = *(const float4*)(B + (size_t)(kn + br1) * N + n0 + bc1);
        }

        // Compute on current buffer
#pragma unroll
        for (int kk = 0; kk < 16; kk += 8) {
            unsigned af[2][4];
#pragma unroll
            for (int mt = 0; mt < 2; mt++) {
                const int mb = wm + mt * 16;
                af[mt][0] = __float_as_uint(As[buf][kk + tg    ][mb + g    ]);
                af[mt][1] = __float_as_uint(As[buf][kk + tg    ][mb + g + 8]);
                af[mt][2] = __float_as_uint(As[buf][kk + tg + 4][mb + g    ]);
                af[mt][3] = __float_as_uint(As[buf][kk + tg + 4][mb + g + 8]);
            }
#pragma unroll
            for (int nt = 0; nt < 8; nt++) {
                unsigned bf[2];
                bf[0] = __float_as_uint(Bs[buf][kk + tg    ][wn + nt * 8 + g]);
                bf[1] = __float_as_uint(Bs[buf][kk + tg + 4][wn + nt * 8 + g]);
                mma8(acc[0][nt], af[0], bf);
                mma8(acc[1][nt], af[1], bf);
            }
        }

        if (hasNext) {
            const int nb = buf ^ 1;
            As[nb][aK + 0][aRow] = tf32f(a0.x);  As[nb][aK + 1][aRow] = tf32f(a0.y);
            As[nb][aK + 2][aRow] = tf32f(a0.z);  As[nb][aK + 3][aRow] = tf32f(a0.w);
            As[nb][aK + 0][aRow + 64] = tf32f(a1.x);  As[nb][aK + 1][aRow + 64] = tf32f(a1.y);
            As[nb][aK + 2][aRow + 64] = tf32f(a1.z);  As[nb][aK + 3][aRow + 64] = tf32f(a1.w);
            Bs[nb][br0][bc0 + 0] = tf32f(b0.x); Bs[nb][br0][bc0 + 1] = tf32f(b0.y);
            Bs[nb][br0][bc0 + 2] = tf32f(b0.z); Bs[nb][br0][bc0 + 3] = tf32f(b0.w);
            Bs[nb][br1][bc1 + 0] = tf32f(b1.x); Bs[nb][br1][bc1 + 1] = tf32f(b1.y);
            Bs[nb][br1][bc1 + 2] = tf32f(b1.z); Bs[nb][br1][bc1 + 3] = tf32f(b1.w);
            __syncthreads();
        }
    }

    // Epilogue
#pragma unroll
    for (int mt = 0; mt < 2; mt++)
#pragma unroll
        for (int nt = 0; nt < 8; nt++)
#pragma unroll
            for (int c = 0; c < 4; c++) {
                const int m = m0 + wm + mt * 16 + g + ((c >= 2) ? 8 : 0);
                const int n = n0 + wn + nt * 8 + 2 * tg + (c & 1);
                const float v = acc[mt][nt][c] + bias[n];
                if (MODE == 0) {
                    C[(size_t)m * N + n] = v;
                } else {
                    const int b    = m >> 11;
                    const int s    = m & 2047;
                    const int head = n >> 6;
                    const int dd   = n & 63;
                    C[((((size_t)b * NH + head) * S_LEN) + s) * HD + dd] = v;
                }
            }
}

// ---------------------------------------------------------------------------
// Flash attention, tf32 tensor cores. 64 q rows per block, 4 warps (16 each).
// KV tiles of 64 via smem (vectorized cvt staging). P stays in registers:
// accumulator->A-fragment permutation done with intra-quad shuffles.
// ---------------------------------------------------------------------------
__global__ __launch_bounds__(128)
void attn_tc(const float* __restrict__ Q, const float* __restrict__ Kp,
             const float* __restrict__ Vp, float* __restrict__ Z)
{
    __shared__ float Ks[64][68];
    __shared__ float Vs[64][68];

    const int tid  = threadIdx.x;
    const int warp = tid >> 5, lane = tid & 31;
    const int g = lane >> 2, tg = lane & 3;
    const int bh   = blockIdx.y;
    const int b    = bh >> 4, head = bh & 15;
    const int q0   = blockIdx.x * 64;
    const int rlo  = warp * 16 + g;

    // Q fragments, pre-scaled by 1/sqrt(64)=0.125, tf32-rounded.
    const float* qlo = Q + ((size_t)bh * S_LEN + q0 + rlo) * HD;
    const float* qhi = qlo + 8 * HD;
    unsigned qf[8][4];
#pragma unroll
    for (int kt = 0; kt < 8; kt++) {
        qf[kt][0] = tf32u(0.125f * qlo[kt * 8 + tg]);
        qf[kt][1] = tf32u(0.125f * qhi[kt * 8 + tg]);
        qf[kt][2] = tf32u(0.125f * qlo[kt * 8 + tg + 4]);
        qf[kt][3] = tf32u(0.125f * qhi[kt * 8 + tg + 4]);
    }

    float oacc[8][4];
#pragma unroll
    for (int nt = 0; nt < 8; nt++)
#pragma unroll
        for (int c = 0; c < 4; c++) oacc[nt][c] = 0.f;
    float m_lo = -1e30f, m_hi = -1e30f, l_lo = 0.f, l_hi = 0.f;

    const float* Kb = Kp + (size_t)bh * S_LEN * HD;
    const float* Vb = Vp + (size_t)bh * S_LEN * HD;

    const unsigned FULL = 0xffffffffu;
    const int src_a = (lane & ~3) | (tg >> 1);   // holds col tg of this quad's P row
    const int src_b = src_a + 2;                 // holds col tg+4
    const bool hi_slot = (tg & 1) != 0;

    for (int kv0 = 0; kv0 < S_LEN; kv0 += 64) {
        __syncthreads();   // previous tile fully consumed
#pragma unroll
        for (int i = 0; i < 8; i++) {
            const int f = i * 128 + tid;
            const int r = f >> 4, c = (f & 15) * 4;
            const float4 k4 = *(const float4*)(Kb + (size_t)(kv0 + r) * HD + c);
            const float4 v4 = *(const float4*)(Vb + (size_t)(kv0 + r) * HD + c);
            float4 kc, vc;
            kc.x = tf32f(k4.x); kc.y = tf32f(k4.y); kc.z = tf32f(k4.z); kc.w = tf32f(k4.w);
            vc.x = tf32f(v4.x); vc.y = tf32f(v4.y); vc.z = tf32f(v4.z); vc.w = tf32f(v4.w);
            *(float4*)&Ks[r][c] = kc;
            *(float4*)&Vs[r][c] = vc;
        }
        __syncthreads();

        // S = Q @ K^T  (scale folded into Q)
        float sacc[8][4];
#pragma unroll
        for (int nt = 0; nt < 8; nt++)
#pragma unroll
            for (int c = 0; c < 4; c++) sacc[nt][c] = 0.f;
#pragma unroll
        for (int kt = 0; kt < 8; kt++) {
#pragma unroll
            for (int nt = 0; nt < 8; nt++) {
                unsigned bf[2];
                bf[0] = __float_as_uint(Ks[nt * 8 + g][kt * 8 + tg]);
                bf[1] = __float_as_uint(Ks[nt * 8 + g][kt * 8 + tg + 4]);
                mma8(sacc[nt], qf[kt], bf);
            }
        }

        // Online softmax (rows rlo and rlo+8)
        float rmax_lo = -1e30f, rmax_hi = -1e30f;
#pragma unroll
        for (int nt = 0; nt < 8; nt++) {
            rmax_lo = fmaxf(rmax_lo, fmaxf(sacc[nt][0], sacc[nt][1]));
            rmax_hi = fmaxf(rmax_hi, fmaxf(sacc[nt][2], sacc[nt][3]));
        }
        rmax_lo = fmaxf(rmax_lo, __shfl_xor_sync(FULL, rmax_lo, 1));
        rmax_lo = fmaxf(rmax_lo, __shfl_xor_sync(FULL, rmax_lo, 2));
        rmax_hi = fmaxf(rmax_hi, __shfl_xor_sync(FULL, rmax_hi, 1));
        rmax_hi = fmaxf(rmax_hi, __shfl_xor_sync(FULL, rmax_hi, 2));

        const float mn_lo = fmaxf(m_lo, rmax_lo);
        const float mn_hi = fmaxf(m_hi, rmax_hi);
        const float corr_lo = __expf(m_lo - mn_lo);
        const float corr_hi = __expf(m_hi - mn_hi);

        float rs_lo = 0.f, rs_hi = 0.f;
#pragma unroll
        for (int nt = 0; nt < 8; nt++) {
            sacc[nt][0] = __expf(sacc[nt][0] - mn_lo);
            sacc[nt][1] = __expf(sacc[nt][1] - mn_lo);
            sacc[nt][2] = __expf(sacc[nt][2] - mn_hi);
            sacc[nt][3] = __expf(sacc[nt][3] - mn_hi);
            rs_lo += sacc[nt][0] + sacc[nt][1];
            rs_hi += sacc[nt][2] + sacc[nt][3];
        }
        rs_lo += __shfl_xor_sync(FULL, rs_lo, 1);
        rs_lo += __shfl_xor_sync(FULL, rs_lo, 2);
        rs_hi += __shfl_xor_sync(FULL, rs_hi, 1);
        rs_hi += __shfl_xor_sync(FULL, rs_hi, 2);

        l_lo = l_lo * corr_lo + rs_lo;
        l_hi = l_hi * corr_hi + rs_hi;
#pragma unroll
        for (int nt = 0; nt < 8; nt++) {
            oacc[nt][0] *= corr_lo; oacc[nt][1] *= corr_lo;
            oacc[nt][2] *= corr_hi; oacc[nt][3] *= corr_hi;
        }
        m_lo = mn_lo; m_hi = mn_hi;

        // O += P @ V ; P(16x8 per kt) permuted acc->A-frag via intra-quad shfl
#pragma unroll
        for (int kt = 0; kt < 8; kt++) {
            const float v0 = __shfl_sync(FULL, sacc[kt][0], src_a);
            const float v1 = __shfl_sync(FULL, sacc[kt][1], src_a);
            const float v2 = __shfl_sync(FULL, sacc[kt][2], src_a);
            const float v3 = __shfl_sync(FULL, sacc[kt][3], src_a);
            const float w0 = __shfl_sync(FULL, sacc[kt][0], src_b);
            const float w1 = __shfl_sync(FULL, sacc[kt][1], src_b);
            const float w2 = __shfl_sync(FULL, sacc[kt][2], src_b);
            const float w3 = __shfl_sync(FULL, sacc[kt][3], src_b);
            unsigned pf[4];
            pf[0] = tf32u(hi_slot ? v1 : v0);   // P[g   ][kt*8 + tg]
            pf[1] = tf32u(hi_slot ? v3 : v2);   // P[g+8 ][kt*8 + tg]
            pf[2] = tf32u(hi_slot ? w1 : w0);   // P[g   ][kt*8 + tg+4]
            pf[3] = tf32u(hi_slot ? w3 : w2);   // P[g+8 ][kt*8 + tg+4]
#pragma unroll
            for (int nt = 0; nt < 8; nt++) {
                unsigned bf[2];
                bf[0] = __float_as_uint(Vs[kt * 8 + tg    ][nt * 8 + g]);
                bf[1] = __float_as_uint(Vs[kt * 8 + tg + 4][nt * 8 + g]);
                mma8(oacc[nt], pf, bf);
            }
        }
    }

    const float inv_lo = 1.f / l_lo;
    const float inv_hi = 1.f / l_hi;
    float* zlo = Z + ((size_t)(b * S_LEN + q0 + rlo)) * EMB + head * HD;
    float* zhi = zlo + (size_t)8 * EMB;
#pragma unroll
    for (int nt = 0; nt < 8; nt++) {
        zlo[nt * 8 + 2 * tg    ] = oacc[nt][0] * inv_lo;
        zlo[nt * 8 + 2 * tg + 1] = oacc[nt][1] * inv_lo;
        zhi[nt * 8 + 2 * tg    ] = oacc[nt][2] * inv_hi;
        zhi[nt * 8 + 2 * tg + 1] = oacc[nt][3] * inv_hi;
    }
}

// ---------------------------------------------------------------------------
extern "C" void kernel_launch(void* const* d_in, const int* in_sizes, int n_in,
                              void* d_out, int out_size)
{
    const float* query = (const float*)d_in[0];
    const float* key_  = (const float*)d_in[1];
    const float* value = (const float*)d_in[2];
    const float* Wq = (const float*)d_in[3];
    const float* bq = (const float*)d_in[4];
    const float* Wk = (const float*)d_in[5];
    const float* bk = (const float*)d_in[6];
    const float* Wv = (const float*)d_in[7];
    const float* bv = (const float*)d_in[8];
    const float* Wo = (const float*)d_in[9];
    const float* bo = (const float*)d_in[10];
    float* out = (float*)d_out;

    float *q, *k, *v, *z;
    cudaGetSymbolAddress((void**)&q, g_q);
    cudaGetSymbolAddress((void**)&k, g_k);
    cudaGetSymbolAddress((void**)&v, g_v);
    cudaGetSymbolAddress((void**)&z, g_z);

    const dim3 gemmGrid(EMB / 128, M_ROWS / 128);   // (8, 32)
    const dim3 attnGrid(S_LEN / 64, BATCH * NH);    // (32, 32)

    gemm_tc<1><<<gemmGrid, 256>>>(query, Wq, bq, q, M_ROWS, EMB, EMB);
    gemm_tc<1><<<gemmGrid, 256>>>(key_,  Wk, bk, k, M_ROWS, EMB, EMB);
    gemm_tc<1><<<gemmGrid, 256>>>(value, Wv, bv, v, M_ROWS, EMB, EMB);
    attn_tc<<<attnGrid, 128>>>(q, k, v, z);
    gemm_tc<0><<<gemmGrid, 256>>>(z, Wo, bo, out, M_ROWS, EMB, EMB);
}